// round 15
// baseline (speedup 1.0000x reference)
#include <cuda_runtime.h>
#include <cuda_bf16.h>
#include <math.h>
#include <stdint.h>

// ---------------- problem constants ----------------
#define BATCH 64
#define NN    1023
#define PROC  511
#define HH    512
#define EE    512
#define VOCAB 32
#define OPS   16
#define GG    2048        // packed gates q = 4*h + {i,f,g,o}

// ---------------- GEMM tiling (proven config) ----------------
#define BM 128
#define BN 128
#define BK 64
#define NTILES (GG / BN)  // 16
#define TSTRIDE 144
#define ST_SZ  (256 * TSTRIDE)      // 36864
#define NSTAGE 3
#define SMEM_BYTES (NSTAGE * ST_SZ) // 110592 -> 2 CTAs/SM

#define ROWCAP 8224       // per-side rows in dedup GEMM: 32 U rows + up to 8192 slots

// ---------------- device scratch ----------------
__device__ __nv_bfloat16 g_hhi[(size_t)PROC * BATCH * HH];
__device__ float g_c[(size_t)PROC * BATCH * HH];
__device__ float g_hroot[BATCH * HH];
__device__ __nv_bfloat16 g_Whi[(size_t)GG * 1024];
__device__ float g_P[VOCAB * GG];
__device__ float g_biasp[GG];
__device__ float g_wlast[GG];
__device__ int   g_tnode[PROC * BATCH];
__device__ float g_dnode[PROC * BATCH];
__device__ float g_part[32u * 64u * 2048u];          // split-K partials (d<=4)
__device__ __nv_bfloat16 g_Aext[(size_t)2 * ROWCAP * 512];  // dedup GEMM A (V rows + dh slots)
__device__ float g_gout[(size_t)2 * ROWCAP * GG];    // dedup GEMM output (U + corr)
__device__ int   g_slot[2 * 128 * 64];               // slot+1 per (side, d7-local node, b)
__device__ unsigned g_cnt[2];

// ---------------- helpers ----------------
__device__ __forceinline__ uint32_t smem_u32(const void* p) {
    uint32_t a;
    asm("{ .reg .u64 t; cvta.to.shared.u64 t, %1; cvt.u32.u64 %0, t; }" : "=r"(a) : "l"(p));
    return a;
}
__device__ __forceinline__ void cp16(uint32_t dst, const void* src) {
    asm volatile("cp.async.cg.shared.global [%0], [%1], 16;" :: "r"(dst), "l"(src));
}
#define CP_COMMIT() asm volatile("cp.async.commit_group;" ::: "memory")
template <int N>
__device__ __forceinline__ void cp_wait() {
    asm volatile("cp.async.wait_group %0;" :: "n"(N) : "memory");
}
__device__ __forceinline__ void ldm_x4(uint32_t* d, uint32_t addr) {
    asm volatile("ldmatrix.sync.aligned.m8n8.x4.shared.b16 {%0,%1,%2,%3}, [%4];"
                 : "=r"(d[0]), "=r"(d[1]), "=r"(d[2]), "=r"(d[3]) : "r"(addr));
}
__device__ __forceinline__ void mma_bf16(float* c, const uint32_t* a, const uint32_t* b) {
    asm volatile(
        "mma.sync.aligned.m16n8k16.row.col.f32.bf16.bf16.f32 "
        "{%0,%1,%2,%3}, {%4,%5,%6,%7}, {%8,%9}, {%0,%1,%2,%3};"
        : "+f"(c[0]), "+f"(c[1]), "+f"(c[2]), "+f"(c[3])
        : "r"(a[0]), "r"(a[1]), "r"(a[2]), "r"(a[3]), "r"(b[0]), "r"(b[1]));
}
// single-MUFU activations: tanh.approx.f32 (err ~2^-11, below bf16 noise floor)
__device__ __forceinline__ float ftanh(float x) {
    float y;
    asm("tanh.approx.f32 %0, %1;" : "=f"(y) : "f"(x));
    return y;
}
__device__ __forceinline__ float fsig(float x) {
    return fmaf(ftanh(0.5f * x), 0.5f, 0.5f);
}
__device__ __forceinline__ int packed_row(int q) { return (q & 3) * 1024 + (q >> 2); }

__device__ __forceinline__ void lstm_cell(float4 g, int t, float dd, int q, float c0,
                                          float& hn, float& cn) {
    float4 pv = *(const float4*)&g_P[t * GG + q];
    float4 wl = *(const float4*)&g_wlast[q];
    float4 bp = *(const float4*)&g_biasp[q];
    float gi = g.x + pv.x + dd * wl.x + bp.x;
    float gf = g.y + pv.y + dd * wl.y + bp.y;
    float gg = g.z + pv.z + dd * wl.z + bp.z;
    float go = g.w + pv.w + dd * wl.w + bp.w;
    cn = fsig(gf) * c0 + fsig(gi) * ftanh(gg);
    hn = fsig(go) * ftanh(cn);
}

// leaf (d=8) cell: children are zeros
__device__ __forceinline__ void leaf_hc(int t, float dd, int h, float& hn, float& cn) {
    int q = 4 * h;
    float4 pv = *(const float4*)&g_P[t * GG + q];
    float4 wl = *(const float4*)&g_wlast[q];
    float4 bp = *(const float4*)&g_biasp[q];
    float gi = pv.x + dd * wl.x + bp.x;
    float gg = pv.z + dd * wl.z + bp.z;
    float go = pv.w + dd * wl.w + bp.w;
    cn = fsig(gi) * ftanh(gg);
    hn = fsig(go) * ftanh(cn);
}
// leaf c only (cheaper: 2 MUFU)
__device__ __forceinline__ float leaf_c(int t, float dd, int h) {
    int q = 4 * h;
    float4 pv = *(const float4*)&g_P[t * GG + q];
    float4 wl = *(const float4*)&g_wlast[q];
    float4 bp = *(const float4*)&g_biasp[q];
    float gi = pv.x + dd * wl.x + bp.x;
    float gg = pv.z + dd * wl.z + bp.z;
    return fsig(gi) * ftanh(gg);
}

// ---------------- fused prep: bias/wlast + W_hh conv + P table + node meta --------
__global__ void fused_prep_kernel(const float* __restrict__ W_ih,
                                  const float* __restrict__ b_ih,
                                  const float* __restrict__ b_hh,
                                  const float* __restrict__ W_hh,
                                  const float* __restrict__ emb_table,
                                  const int* __restrict__ node_types,
                                  const float* __restrict__ node_args) {
    __shared__ float se[EE];
    int bx = blockIdx.x;
    if (bx < 8) {
        if (bx == 0 && threadIdx.x < 2) g_cnt[threadIdx.x] = 0;
        int q = bx * 256 + threadIdx.x;
        int r = packed_row(q);
        g_biasp[q] = b_ih[r] + b_hh[r];
        g_wlast[q] = W_ih[(size_t)r * EE + (EE - 1)];
        return;
    }
    bx -= 8;
    if (bx < GG) {
        int r = packed_row(bx);
        for (int k = threadIdx.x; k < 1024; k += 256)
            g_Whi[(size_t)bx * 1024 + k] = __float2bfloat16(W_hh[(size_t)r * 1024 + k]);
        return;
    }
    bx -= GG;
    if (bx < 256) {   // compP: t = bx>>3, qblk = bx&7
        int t = bx >> 3;
        for (int i = threadIdx.x; i < EE; i += 256)
            se[i] = emb_table[(size_t)t * EE + i];
        __syncthreads();
        int q = (bx & 7) * 256 + threadIdx.x;
        int r = packed_row(q);
        const float4* w = (const float4*)(W_ih + (size_t)r * EE);
        const float4* s4 = (const float4*)se;
        float acc = 0.f;
#pragma unroll 8
        for (int e = 0; e < EE / 4; e++) {
            float4 a = s4[e], b = w[e];
            acc += a.x * b.x + a.y * b.y + a.z * b.z + a.w * b.w;
        }
        g_P[t * GG + q] = acc;
        return;
    }
    bx -= 256;
    int i = bx * 256 + threadIdx.x;   // node_meta
    if (i >= PROC * BATCH) return;
    int node = i >> 6;
    int b = i & 63;
    int t = node_types[(size_t)b * NN + node];
    g_tnode[i] = t;
    float d = 0.f;
    if (t <= 1)
        d = node_args[(size_t)b * NN + node] - emb_table[(size_t)t * EE + (EE - 1)];
    g_dnode[i] = d;
}

// ---------------- fused compV + gather ----------------
// blocks 0..31: V rows into A_ext (both sides); blocks 32..287: gather Δh rows
__global__ void compv_gather_kernel() {
    int bx = blockIdx.x;
    if (bx < VOCAB) {
        int t = bx;
#pragma unroll
        for (int j = 0; j < 2; j++) {
            int h = threadIdx.x + 256 * j;
            float hn, cn;
            leaf_hc(t, 0.f, h, hn, cn);
            __nv_bfloat16 v = __float2bfloat16(hn);
            g_Aext[((size_t)0 * ROWCAP + t) * 512 + h] = v;
            g_Aext[((size_t)1 * ROWCAP + t) * 512 + h] = v;
        }
        return;
    }
    const int m = 255 + (bx - VOCAB);        // d=8 node 255..510
    const int lane = threadIdx.x & 31;
    const int wi = threadIdx.x >> 5;
    const int side = (m & 1) ? 0 : 1;        // odd = left child
    const int po = ((m - 1) >> 1) - 127;     // parent local index 0..127
#pragma unroll 1
    for (int j = 0; j < 8; j++) {
        const int b = wi * 8 + j;
        const int ni = m * BATCH + b;
        const int t = g_tnode[ni];
        const int sidx = side * 8192 + po * 64 + b;
        if (t <= 1) {
            const float dd = g_dnode[ni];
            int slot = 0;
            if (lane == 0) slot = (int)atomicAdd(&g_cnt[side], 1u);
            slot = __shfl_sync(0xffffffffu, slot, 0);
            if (lane == 0) g_slot[sidx] = slot + 1;
#pragma unroll 4
            for (int kc = 0; kc < 16; kc++) {
                int k = kc * 32 + lane;
                float h1, c1, h0, c0;
                leaf_hc(t, dd, k, h1, c1);
                leaf_hc(t, 0.f, k, h0, c0);
                g_Aext[((size_t)side * ROWCAP + 32 + slot) * 512 + k] =
                    __float2bfloat16(h1 - h0);
            }
        } else {
            if (lane == 0) g_slot[sidx] = 0;
        }
    }
}

// ---------------- dedup GEMM: g_gout[side][row][q] = A_ext[side][row] . W_side[q] ----
__global__ void __launch_bounds__(256, 2) corrmma_kernel() {
    extern __shared__ char smem[];
    uint32_t sb = smem_u32(smem);

    const int side = blockIdx.z;
    const int row0 = blockIdx.x * 128;
    const unsigned cnt = *(volatile unsigned*)&g_cnt[side];
    if (row0 >= (int)(32u + cnt)) return;
    const int q0 = blockIdx.y * BN;

    const int tid = threadIdx.x;
    const int lane = tid & 31;
    const int wid = tid >> 5;
    const int warp_m = wid & 3;
    const int warp_n = wid >> 2;

    float acc[2][8][4];
#pragma unroll
    for (int mt = 0; mt < 2; mt++)
#pragma unroll
        for (int nt = 0; nt < 8; nt++)
#pragma unroll
            for (int i = 0; i < 4; i++) acc[mt][nt][i] = 0.f;

    auto issue = [&](int kc) {
        const int stage = kc % NSTAGE;
        const int k0 = kc * BK;
        const uint32_t base = sb + stage * ST_SZ;
#pragma unroll
        for (int it = 0; it < 8; it++) {
            int i = tid + it * 256;
            int r = i >> 3, cg = i & 7;
            const void* src;
            if (r < 128)
                src = g_Aext + ((size_t)side * ROWCAP + row0 + r) * 512 + k0 + cg * 8;
            else
                src = g_Whi + (size_t)(q0 + r - 128) * 1024 + side * 512 + k0 + cg * 8;
            cp16(base + (uint32_t)(r * TSTRIDE + cg * 16), src);
        }
    };

    issue(0); CP_COMMIT();
    issue(1); CP_COMMIT();

    const uint32_t a_base = (uint32_t)((warp_m * 32 + (lane & 15)) * TSTRIDE + (lane >> 4) * 16);
    const uint32_t b_base = (uint32_t)(128 * TSTRIDE
                             + (warp_n * 64 + ((lane >> 4) << 3) + (lane & 7)) * TSTRIDE
                             + (((lane >> 3) & 1) << 4));

    for (int kc = 0; kc < 8; kc++) {     // K = 512
        if (kc < 7) cp_wait<1>(); else cp_wait<0>();
        __syncthreads();
        if (kc + 2 < 8) { issue(kc + 2); CP_COMMIT(); }
        const uint32_t base = sb + (uint32_t)((kc % NSTAGE) * ST_SZ);
#pragma unroll
        for (int kt = 0; kt < 4; kt++) {
            uint32_t a[2][4];
            ldm_x4(a[0], base + a_base + kt * 32);
            ldm_x4(a[1], base + a_base + 16 * TSTRIDE + kt * 32);
#pragma unroll
            for (int ng = 0; ng < 4; ng++) {
                uint32_t bh[4];
                ldm_x4(bh, base + b_base + ng * 16 * TSTRIDE + kt * 32);
#pragma unroll
                for (int half = 0; half < 2; half++)
#pragma unroll
                    for (int mt = 0; mt < 2; mt++)
                        mma_bf16(acc[mt][ng * 2 + half], a[mt], bh + 2 * half);
            }
        }
    }

    // direct store of raw gate sums
#pragma unroll
    for (int mt = 0; mt < 2; mt++) {
        const int rr = row0 + warp_m * 32 + mt * 16 + (lane >> 2);
#pragma unroll
        for (int nt = 0; nt < 8; nt++) {
            const int qq = q0 + warp_n * 64 + nt * 8 + (lane & 3) * 2;
            *(float2*)&g_gout[((size_t)side * ROWCAP + rr) * GG + qq] =
                make_float2(acc[mt][nt][0], acc[mt][nt][1]);
            *(float2*)&g_gout[((size_t)side * ROWCAP + rr + 8) * GG + qq] =
                make_float2(acc[mt][nt][2], acc[mt][nt][3]);
        }
    }
}

// ---------------- d=7 level: gates = U_L[tl] + U_R[tr] (+corr); c0 on the fly -----
// one node per block (round-13 proven config: latency hidden by 1024 blocks)
__global__ void d7_epilogue_kernel() {
    extern __shared__ float sU[];            // [2][32][256] = 64KB
    const int n = 127 + blockIdx.x;
    const int q0 = blockIdx.y * 256;
    const int tid = threadIdx.x;
    for (int idx = tid; idx < 2 * VOCAB * 256; idx += 256) {
        int s = idx >> 13, rem = idx & 8191, t = rem >> 8, j = rem & 255;
        sU[idx] = g_gout[((size_t)s * ROWCAP + t) * GG + q0 + j];
    }
    __syncthreads();

    const int hl = tid & 63;
    const int bq = tid >> 6;
    const int h = (q0 >> 2) + hl;
    const int q = q0 + 4 * hl;
#pragma unroll 1
    for (int bi = 0; bi < 16; bi++) {
        const int b = bq * 16 + bi;
        const int ni = n * BATCH + b;
        const int li = (2 * n + 1) * BATCH + b;
        const int t_node = g_tnode[ni];
        const float dd = g_dnode[ni];
        const int tl = g_tnode[li];
        const float ddl = g_dnode[li];
        const int tr = g_tnode[li + BATCH];
        const int sl = g_slot[(n - 127) * 64 + b];
        const int sr = g_slot[8192 + (n - 127) * 64 + b];
        float4 gL = *(const float4*)&sU[tl * 256 + 4 * hl];
        float4 gR = *(const float4*)&sU[8192 + tr * 256 + 4 * hl];
        float4 g = make_float4(gL.x + gR.x, gL.y + gR.y, gL.z + gR.z, gL.w + gR.w);
        if (sl) {
            float4 cr = *(const float4*)&g_gout[((size_t)0 * ROWCAP + 32 + sl - 1) * GG + q];
            g.x += cr.x; g.y += cr.y; g.z += cr.z; g.w += cr.w;
        }
        if (sr) {
            float4 cr = *(const float4*)&g_gout[((size_t)1 * ROWCAP + 32 + sr - 1) * GG + q];
            g.x += cr.x; g.y += cr.y; g.z += cr.z; g.w += cr.w;
        }
        float c0 = leaf_c(tl, ddl, h);   // left child is a d=8 leaf: closed form
        float hn, cn;
        lstm_cell(g, t_node, dd, q, c0, hn, cn);
        size_t o = (size_t)ni * HH + h;
        g_hhi[o] = __float2bfloat16(hn);
        g_c[o] = cn;
    }
}

// ---------------- level GEMM (d<=6): proven kernel ----------------
__global__ void __launch_bounds__(256, 2) level_mma_kernel(int first, int count, int ksplit) {
    extern __shared__ char smem[];
    uint32_t sb = smem_u32(smem);

    const int tid = threadIdx.x;
    const int lane = tid & 31;
    const int wid = tid >> 5;
    const int warp_m = wid & 3;
    const int warp_n = wid >> 2;

    const int p = blockIdx.x;
    const int n0 = first + 2 * p;
    const int n1 = (n0 + 1 <= first + count - 1) ? n0 + 1 : n0;
    const int q0 = blockIdx.y * BN;
    const int ks = blockIdx.z;
    const int chunks = 16 / ksplit;
    const int kc0 = ks * chunks;
    const int kcE = kc0 + chunks;

    float acc[2][8][4];
#pragma unroll
    for (int mt = 0; mt < 2; mt++)
#pragma unroll
        for (int nt = 0; nt < 8; nt++)
#pragma unroll
            for (int i = 0; i < 4; i++) acc[mt][nt][i] = 0.f;

    auto issue = [&](int kc) {
        const int stage = (kc - kc0) % NSTAGE;
        const int k0 = kc * BK;
        const int cbase = (k0 < 512) ? 1 : 2;
        const int kk = k0 & 511;
        const uint32_t base = sb + stage * ST_SZ;
#pragma unroll
        for (int it = 0; it < 8; it++) {
            int i = tid + it * 256;
            int r = i >> 3, cg = i & 7;
            const void* src;
            if (r < 128) {
                int node = (r < 64) ? n0 : n1;
                src = g_hhi + ((size_t)(2 * node + cbase) * BATCH + (r & 63)) * HH + kk + cg * 8;
            } else {
                src = g_Whi + (size_t)(q0 + r - 128) * 1024 + k0 + cg * 8;
            }
            cp16(base + (uint32_t)(r * TSTRIDE + cg * 16), src);
        }
    };

    issue(kc0);     CP_COMMIT();
    issue(kc0 + 1); CP_COMMIT();

    const uint32_t a_base = (uint32_t)((warp_m * 32 + (lane & 15)) * TSTRIDE + (lane >> 4) * 16);
    const uint32_t b_base = (uint32_t)(128 * TSTRIDE
                             + (warp_n * 64 + ((lane >> 4) << 3) + (lane & 7)) * TSTRIDE
                             + (((lane >> 3) & 1) << 4));

    for (int kc = kc0; kc < kcE; kc++) {
        if (kc < kcE - 1) cp_wait<1>(); else cp_wait<0>();
        __syncthreads();
        if (kc + 2 < kcE) { issue(kc + 2); CP_COMMIT(); }
        const uint32_t base = sb + (uint32_t)(((kc - kc0) % NSTAGE) * ST_SZ);
#pragma unroll
        for (int kt = 0; kt < 4; kt++) {
            uint32_t a[2][4];
            ldm_x4(a[0], base + a_base + kt * 32);
            ldm_x4(a[1], base + a_base + 16 * TSTRIDE + kt * 32);
#pragma unroll
            for (int ng = 0; ng < 4; ng++) {
                uint32_t bh[4];
                ldm_x4(bh, base + b_base + ng * 16 * TSTRIDE + kt * 32);
#pragma unroll
                for (int half = 0; half < 2; half++)
#pragma unroll
                    for (int mt = 0; mt < 2; mt++)
                        mma_bf16(acc[mt][ng * 2 + half], a[mt], bh + 2 * half);
            }
        }
    }

    const int lr = (lane >> 2) + (lane & 1) * 8;
    const int hq = (q0 >> 2) + warp_n * 16 + ((lane & 3) >> 1);

#pragma unroll
    for (int mt = 0; mt < 2; mt++) {
        const int r = warp_m * 32 + mt * 16 + lr;
        const int node = (r < 64) ? n0 : n1;
        const bool skip = (r >= 64) && (n1 == n0);
        const int b = r & 63;
        const int ni = node * BATCH + b;
        const int t = g_tnode[ni];
        const float dd = g_dnode[ni];
        const int left = 2 * node + 1;
#pragma unroll
        for (int nt = 0; nt < 8; nt++) {
            float x0 = __shfl_xor_sync(0xffffffffu, acc[mt][nt][0], 1);
            float x1 = __shfl_xor_sync(0xffffffffu, acc[mt][nt][1], 1);
            float x2 = __shfl_xor_sync(0xffffffffu, acc[mt][nt][2], 1);
            float x3 = __shfl_xor_sync(0xffffffffu, acc[mt][nt][3], 1);
            float4 g;
            if (lane & 1) g = make_float4(x2, x3, acc[mt][nt][2], acc[mt][nt][3]);
            else          g = make_float4(acc[mt][nt][0], acc[mt][nt][1], x0, x1);
            if (skip) continue;
            const int h = hq + nt * 2;
            const int q = 4 * h;
            if (ksplit == 1) {
                float c0 = g_c[((size_t)left * BATCH + b) * HH + h];
                float hn, cn;
                lstm_cell(g, t, dd, q, c0, hn, cn);
                size_t o = ((size_t)node * BATCH + b) * HH + h;
                g_hhi[o] = __float2bfloat16(hn);
                g_c[o] = cn;
                if (node == 0) g_hroot[b * HH + h] = hn;
            } else {
                int nl = node - first;
                size_t dst = (((size_t)(ks * count + nl) * BATCH + b) * (size_t)GG) + q;
                *(float4*)&g_part[dst] = g;
            }
        }
    }
}

// ---------------- split-K reduction + LSTM ----------------
__global__ void level_reduce_kernel(int first, int count, int ksplit) {
    int nl = blockIdx.x;
    int node = first + nl;
    int q0 = blockIdx.y * BN;
    int tid = threadIdx.x;
    for (int idx = tid; idx < 64 * 32; idx += 256) {
        int b = idx >> 5, hg = idx & 31;
        int q = q0 + hg * 4;
        int hidx = (q0 >> 2) + hg;
        float4 s = make_float4(0.f, 0.f, 0.f, 0.f);
        for (int ks = 0; ks < ksplit; ks++) {
            const float4 v = *(const float4*)&g_part[(((size_t)(ks * count + nl) * BATCH + b) * (size_t)GG) + q];
            s.x += v.x; s.y += v.y; s.z += v.z; s.w += v.w;
        }
        int ni = node * BATCH + b;
        int t = g_tnode[ni];
        float dd = g_dnode[ni];
        float c0 = g_c[((size_t)(2 * node + 1) * BATCH + b) * HH + hidx];
        float hn, cn;
        lstm_cell(s, t, dd, q, c0, hn, cn);
        size_t o = ((size_t)node * BATCH + b) * HH + hidx;
        g_hhi[o] = __float2bfloat16(hn);
        g_c[o] = cn;
        if (node == 0) g_hroot[b * HH + hidx] = hn;
    }
}

// ---------------- output head (exact math kept) ----------------
__global__ void head_kernel(const float* __restrict__ W1, const float* __restrict__ b1,
                            const float* __restrict__ W2, const float* __restrict__ b2,
                            const float* __restrict__ validity, float* __restrict__ out) {
    int b = blockIdx.x;
    __shared__ float sh[HH];
    __shared__ float sx[HH];
    __shared__ float slog[OPS];
    const float* rh = g_hroot + (size_t)b * HH;
    for (int i = threadIdx.x; i < HH; i += blockDim.x) sh[i] = rh[i];
    __syncthreads();
    for (int j = threadIdx.x; j < HH; j += blockDim.x) {
        float acc = b1[j];
        const float4* w = (const float4*)(W1 + (size_t)j * HH);
        const float4* s4 = (const float4*)sh;
#pragma unroll 8
        for (int e = 0; e < HH / 4; e++) {
            float4 a = s4[e], ww = w[e];
            acc += a.x * ww.x + a.y * ww.y + a.z * ww.z + a.w * ww.w;
        }
        sx[j] = fmaxf(acc, 0.f);
    }
    __syncthreads();
    int warp = threadIdx.x >> 5, lane = threadIdx.x & 31;
    for (int o = warp; o < OPS; o += 8) {
        float acc = 0.f;
        const float* w = W2 + (size_t)o * HH;
        for (int e = lane; e < HH; e += 32) acc += sx[e] * w[e];
#pragma unroll
        for (int off = 16; off; off >>= 1) acc += __shfl_xor_sync(0xffffffff, acc, off);
        if (lane == 0) slog[o] = acc + b2[o] + logf(validity[b * OPS + o]);
    }
    __syncthreads();
    if (threadIdx.x == 0) {
        float mx = -1e30f;
        float v[OPS];
        for (int o = 0; o < OPS; o++) { v[o] = slog[o] / 3.0f; if (v[o] > mx) mx = v[o]; }
        float s = 0.f;
        for (int o = 0; o < OPS; o++) { v[o] = expf(v[o] - mx); s += v[o]; }
        float inv = 1.0f / s;
        for (int o = 0; o < OPS; o++) out[b * OPS + o] = v[o] * inv;
    }
}

// ---------------- launch ----------------
extern "C" void kernel_launch(void* const* d_in, const int* in_sizes, int n_in,
                              void* d_out, int out_size) {
    const int*   node_types = (const int*)d_in[0];
    const float* node_args  = (const float*)d_in[1];
    const float* validity   = (const float*)d_in[2];
    const float* emb_table  = (const float*)d_in[3];
    const float* W_ih       = (const float*)d_in[4];
    const float* W_hh       = (const float*)d_in[5];
    const float* b_ih       = (const float*)d_in[6];
    const float* b_hh       = (const float*)d_in[7];
    const float* W1         = (const float*)d_in[8];
    const float* b1         = (const float*)d_in[9];
    const float* W2         = (const float*)d_in[10];
    const float* b2         = (const float*)d_in[11];
    float* out = (float*)d_out;

    static bool attr_set = false;
    if (!attr_set) {
        cudaFuncSetAttribute(level_mma_kernel,
                             cudaFuncAttributeMaxDynamicSharedMemorySize, SMEM_BYTES);
        cudaFuncSetAttribute(corrmma_kernel,
                             cudaFuncAttributeMaxDynamicSharedMemorySize, SMEM_BYTES);
        cudaFuncSetAttribute(d7_epilogue_kernel,
                             cudaFuncAttributeMaxDynamicSharedMemorySize, 65536);
        attr_set = true;
    }

    // fused prep: 8 (bias/wlast+cnt reset) + 2048 (W_hh) + 256 (P) + 128 (meta)
    fused_prep_kernel<<<8 + GG + 256 + 128, 256>>>(W_ih, b_ih, b_hh, W_hh, emb_table,
                                                   node_types, node_args);

    // d=8 + d=7 via dedup path
    compv_gather_kernel<<<VOCAB + 256, 256>>>();
    corrmma_kernel<<<dim3(ROWCAP / 128 + 1, NTILES, 2), 256, SMEM_BYTES>>>();
    d7_epilogue_kernel<<<dim3(128, 8), 256, 65536>>>();

    // levels d=6..0
    for (int d = 6; d >= 0; --d) {
        int first = (1 << d) - 1;
        int count = 1 << d;
        int sk = (d >= 5) ? 1 : (d == 4 ? 2 : (d == 3 ? 4 : 8));
        dim3 grid((count + 1) / 2, NTILES, sk);
        level_mma_kernel<<<grid, 256, SMEM_BYTES>>>(first, count, sk);
        if (sk > 1)
            level_reduce_kernel<<<dim3(count, NTILES), 256>>>(first, count, sk);
    }

    head_kernel<<<BATCH, 256>>>(W1, b1, W2, b2, validity, out);
}

// round 16
// speedup vs baseline: 1.1345x; 1.1345x over previous
#include <cuda_runtime.h>
#include <cuda_bf16.h>
#include <math.h>
#include <stdint.h>

// ---------------- problem constants ----------------
#define BATCH 64
#define NN    1023
#define PROC  511
#define HH    512
#define EE    512
#define VOCAB 32
#define OPS   16
#define GG    2048        // packed gates q = 4*h + {i,f,g,o}

// ---------------- GEMM tiling (proven config) ----------------
#define BM 128
#define BN 128
#define BK 64
#define NTILES (GG / BN)  // 16
#define TSTRIDE 144
#define ST_SZ  (256 * TSTRIDE)      // 36864
#define NSTAGE 3
#define SMEM_BYTES (NSTAGE * ST_SZ) // 110592 -> 2 CTAs/SM

#define ROWCAP 8224       // per-side rows in dedup GEMM: 32 U rows + up to 8192 slots

// ---------------- device scratch ----------------
__device__ __nv_bfloat16 g_hhi[(size_t)PROC * BATCH * HH];
__device__ float g_c[(size_t)PROC * BATCH * HH];
__device__ float g_hroot[BATCH * HH];
__device__ __nv_bfloat16 g_Whi[(size_t)GG * 1024];
__device__ float g_P[VOCAB * GG];
__device__ float g_biasp[GG];
__device__ float g_wlast[GG];
__device__ int   g_tnode[PROC * BATCH];
__device__ float g_dnode[PROC * BATCH];
__device__ float g_part[32u * 64u * 2048u];          // split-K partials (d<=4)
__device__ __nv_bfloat16 g_Aext[(size_t)2 * ROWCAP * 512];  // dedup GEMM A (V rows + dh slots)
__device__ float g_gout[(size_t)2 * ROWCAP * GG];    // dedup GEMM output (U + corr)
__device__ int   g_slot[2 * 128 * 64];               // slot+1 per (side, d7-local node, b)
__device__ unsigned g_cnt[2];

// ---------------- helpers ----------------
__device__ __forceinline__ uint32_t smem_u32(const void* p) {
    uint32_t a;
    asm("{ .reg .u64 t; cvta.to.shared.u64 t, %1; cvt.u32.u64 %0, t; }" : "=r"(a) : "l"(p));
    return a;
}
__device__ __forceinline__ void cp16(uint32_t dst, const void* src) {
    asm volatile("cp.async.cg.shared.global [%0], [%1], 16;" :: "r"(dst), "l"(src));
}
#define CP_COMMIT() asm volatile("cp.async.commit_group;" ::: "memory")
template <int N>
__device__ __forceinline__ void cp_wait() {
    asm volatile("cp.async.wait_group %0;" :: "n"(N) : "memory");
}
__device__ __forceinline__ void ldm_x4(uint32_t* d, uint32_t addr) {
    asm volatile("ldmatrix.sync.aligned.m8n8.x4.shared.b16 {%0,%1,%2,%3}, [%4];"
                 : "=r"(d[0]), "=r"(d[1]), "=r"(d[2]), "=r"(d[3]) : "r"(addr));
}
__device__ __forceinline__ void mma_bf16(float* c, const uint32_t* a, const uint32_t* b) {
    asm volatile(
        "mma.sync.aligned.m16n8k16.row.col.f32.bf16.bf16.f32 "
        "{%0,%1,%2,%3}, {%4,%5,%6,%7}, {%8,%9}, {%0,%1,%2,%3};"
        : "+f"(c[0]), "+f"(c[1]), "+f"(c[2]), "+f"(c[3])
        : "r"(a[0]), "r"(a[1]), "r"(a[2]), "r"(a[3]), "r"(b[0]), "r"(b[1]));
}
// single-MUFU activations: tanh.approx.f32 (err ~2^-11, below bf16 noise floor)
__device__ __forceinline__ float ftanh(float x) {
    float y;
    asm("tanh.approx.f32 %0, %1;" : "=f"(y) : "f"(x));
    return y;
}
__device__ __forceinline__ float fsig(float x) {
    return fmaf(ftanh(0.5f * x), 0.5f, 0.5f);
}
__device__ __forceinline__ int packed_row(int q) { return (q & 3) * 1024 + (q >> 2); }

__device__ __forceinline__ void lstm_cell(float4 g, int t, float dd, int q, float c0,
                                          float& hn, float& cn) {
    float4 pv = *(const float4*)&g_P[t * GG + q];
    float4 wl = *(const float4*)&g_wlast[q];
    float4 bp = *(const float4*)&g_biasp[q];
    float gi = g.x + pv.x + dd * wl.x + bp.x;
    float gf = g.y + pv.y + dd * wl.y + bp.y;
    float gg = g.z + pv.z + dd * wl.z + bp.z;
    float go = g.w + pv.w + dd * wl.w + bp.w;
    cn = fsig(gf) * c0 + fsig(gi) * ftanh(gg);
    hn = fsig(go) * ftanh(cn);
}

// leaf (d=8) cell: children are zeros
__device__ __forceinline__ void leaf_hc(int t, float dd, int h, float& hn, float& cn) {
    int q = 4 * h;
    float4 pv = *(const float4*)&g_P[t * GG + q];
    float4 wl = *(const float4*)&g_wlast[q];
    float4 bp = *(const float4*)&g_biasp[q];
    float gi = pv.x + dd * wl.x + bp.x;
    float gg = pv.z + dd * wl.z + bp.z;
    float go = pv.w + dd * wl.w + bp.w;
    cn = fsig(gi) * ftanh(gg);
    hn = fsig(go) * ftanh(cn);
}
// leaf c only (cheaper: 2 MUFU)
__device__ __forceinline__ float leaf_c(int t, float dd, int h) {
    int q = 4 * h;
    float4 pv = *(const float4*)&g_P[t * GG + q];
    float4 wl = *(const float4*)&g_wlast[q];
    float4 bp = *(const float4*)&g_biasp[q];
    float gi = pv.x + dd * wl.x + bp.x;
    float gg = pv.z + dd * wl.z + bp.z;
    return fsig(gi) * ftanh(gg);
}

// ---------------- prep kernels (separate launches: measured faster than fused) ----
__global__ void prep_small_kernel(const float* __restrict__ W_ih,
                                  const float* __restrict__ b_ih,
                                  const float* __restrict__ b_hh) {
    int q = blockIdx.x * blockDim.x + threadIdx.x;
    if (q >= GG) return;
    int r = packed_row(q);
    g_biasp[q] = b_ih[r] + b_hh[r];
    g_wlast[q] = W_ih[(size_t)r * EE + (EE - 1)];
}

__global__ void conv_whh_kernel(const float* __restrict__ W_hh) {
    int q = blockIdx.x;
    int r = packed_row(q);
    for (int k = threadIdx.x; k < 1024; k += 256)
        g_Whi[(size_t)q * 1024 + k] = __float2bfloat16(W_hh[(size_t)r * 1024 + k]);
}

__global__ void compP_kernel(const float* __restrict__ emb_table,
                             const float* __restrict__ W_ih) {
    __shared__ float se[EE];
    int t = blockIdx.x;
    for (int i = threadIdx.x; i < EE; i += blockDim.x)
        se[i] = emb_table[(size_t)t * EE + i];
    __syncthreads();
    int q = blockIdx.y * blockDim.x + threadIdx.x;
    int r = packed_row(q);
    const float4* w = (const float4*)(W_ih + (size_t)r * EE);
    const float4* s4 = (const float4*)se;
    float acc = 0.f;
#pragma unroll 8
    for (int e = 0; e < EE / 4; e++) {
        float4 a = s4[e], b = w[e];
        acc += a.x * b.x + a.y * b.y + a.z * b.z + a.w * b.w;
    }
    g_P[t * GG + q] = acc;
}

__global__ void node_meta_kernel(const int* __restrict__ node_types,
                                 const float* __restrict__ node_args,
                                 const float* __restrict__ emb_table) {
    int i = blockIdx.x * blockDim.x + threadIdx.x;
    if (i >= PROC * BATCH) return;
    int node = i >> 6;
    int b = i & 63;
    int t = node_types[(size_t)b * NN + node];
    g_tnode[i] = t;
    float d = 0.f;
    if (t <= 1)
        d = node_args[(size_t)b * NN + node] - emb_table[(size_t)t * EE + (EE - 1)];
    g_dnode[i] = d;
}

// ---------------- V table -> A_ext U rows; reset counters ----------------
__global__ void compV_kernel() {
    int t = blockIdx.x;
    if (t == 0 && threadIdx.x < 2) g_cnt[threadIdx.x] = 0;
#pragma unroll
    for (int j = 0; j < 4; j++) {
        int h = threadIdx.x + 128 * j;
        float hn, cn;
        leaf_hc(t, 0.f, h, hn, cn);
        __nv_bfloat16 v = __float2bfloat16(hn);
        g_Aext[((size_t)0 * ROWCAP + t) * 512 + h] = v;
        g_Aext[((size_t)1 * ROWCAP + t) * 512 + h] = v;
    }
}

// ---------------- gather int-typed d=8 children; write Δh rows ----------------
__global__ void gather_kernel() {
    const int m = 255 + blockIdx.x;          // d=8 node
    const int lane = threadIdx.x & 31;
    const int wi = threadIdx.x >> 5;
    const int side = (m & 1) ? 0 : 1;        // odd = left child
    const int po = ((m - 1) >> 1) - 127;     // parent local index 0..127
#pragma unroll 1
    for (int j = 0; j < 8; j++) {
        const int b = wi * 8 + j;
        const int ni = m * BATCH + b;
        const int t = g_tnode[ni];
        const int sidx = side * 8192 + po * 64 + b;
        if (t <= 1) {
            const float dd = g_dnode[ni];
            int slot = 0;
            if (lane == 0) slot = (int)atomicAdd(&g_cnt[side], 1u);
            slot = __shfl_sync(0xffffffffu, slot, 0);
            if (lane == 0) g_slot[sidx] = slot + 1;
#pragma unroll 4
            for (int kc = 0; kc < 16; kc++) {
                int k = kc * 32 + lane;
                float h1, c1, h0, c0;
                leaf_hc(t, dd, k, h1, c1);
                leaf_hc(t, 0.f, k, h0, c0);
                g_Aext[((size_t)side * ROWCAP + 32 + slot) * 512 + k] =
                    __float2bfloat16(h1 - h0);
            }
        } else {
            if (lane == 0) g_slot[sidx] = 0;
        }
    }
}

// ---------------- dedup GEMM: g_gout[side][row][q] = A_ext[side][row] . W_side[q] ----
__global__ void __launch_bounds__(256, 2) corrmma_kernel() {
    extern __shared__ char smem[];
    uint32_t sb = smem_u32(smem);

    const int side = blockIdx.z;
    const int row0 = blockIdx.x * 128;
    const unsigned cnt = *(volatile unsigned*)&g_cnt[side];
    if (row0 >= (int)(32u + cnt)) return;
    const int q0 = blockIdx.y * BN;

    const int tid = threadIdx.x;
    const int lane = tid & 31;
    const int wid = tid >> 5;
    const int warp_m = wid & 3;
    const int warp_n = wid >> 2;

    float acc[2][8][4];
#pragma unroll
    for (int mt = 0; mt < 2; mt++)
#pragma unroll
        for (int nt = 0; nt < 8; nt++)
#pragma unroll
            for (int i = 0; i < 4; i++) acc[mt][nt][i] = 0.f;

    auto issue = [&](int kc) {
        const int stage = kc % NSTAGE;
        const int k0 = kc * BK;
        const uint32_t base = sb + stage * ST_SZ;
#pragma unroll
        for (int it = 0; it < 8; it++) {
            int i = tid + it * 256;
            int r = i >> 3, cg = i & 7;
            const void* src;
            if (r < 128)
                src = g_Aext + ((size_t)side * ROWCAP + row0 + r) * 512 + k0 + cg * 8;
            else
                src = g_Whi + (size_t)(q0 + r - 128) * 1024 + side * 512 + k0 + cg * 8;
            cp16(base + (uint32_t)(r * TSTRIDE + cg * 16), src);
        }
    };

    issue(0); CP_COMMIT();
    issue(1); CP_COMMIT();

    const uint32_t a_base = (uint32_t)((warp_m * 32 + (lane & 15)) * TSTRIDE + (lane >> 4) * 16);
    const uint32_t b_base = (uint32_t)(128 * TSTRIDE
                             + (warp_n * 64 + ((lane >> 4) << 3) + (lane & 7)) * TSTRIDE
                             + (((lane >> 3) & 1) << 4));

    for (int kc = 0; kc < 8; kc++) {     // K = 512
        if (kc < 7) cp_wait<1>(); else cp_wait<0>();
        __syncthreads();
        if (kc + 2 < 8) { issue(kc + 2); CP_COMMIT(); }
        const uint32_t base = sb + (uint32_t)((kc % NSTAGE) * ST_SZ);
#pragma unroll
        for (int kt = 0; kt < 4; kt++) {
            uint32_t a[2][4];
            ldm_x4(a[0], base + a_base + kt * 32);
            ldm_x4(a[1], base + a_base + 16 * TSTRIDE + kt * 32);
#pragma unroll
            for (int ng = 0; ng < 4; ng++) {
                uint32_t bh[4];
                ldm_x4(bh, base + b_base + ng * 16 * TSTRIDE + kt * 32);
#pragma unroll
                for (int half = 0; half < 2; half++)
#pragma unroll
                    for (int mt = 0; mt < 2; mt++)
                        mma_bf16(acc[mt][ng * 2 + half], a[mt], bh + 2 * half);
            }
        }
    }

    // direct store of raw gate sums
#pragma unroll
    for (int mt = 0; mt < 2; mt++) {
        const int rr = row0 + warp_m * 32 + mt * 16 + (lane >> 2);
#pragma unroll
        for (int nt = 0; nt < 8; nt++) {
            const int qq = q0 + warp_n * 64 + nt * 8 + (lane & 3) * 2;
            *(float2*)&g_gout[((size_t)side * ROWCAP + rr) * GG + qq] =
                make_float2(acc[mt][nt][0], acc[mt][nt][1]);
            *(float2*)&g_gout[((size_t)side * ROWCAP + rr + 8) * GG + qq] =
                make_float2(acc[mt][nt][2], acc[mt][nt][3]);
        }
    }
}

// ---------------- d=7 level: gates = U_L[tl] + U_R[tr] (+corr); c0 on the fly -----
// 128-column q tiles -> 32KB smem -> 2 CTAs/SM (occupancy fix)
__global__ void d7_epilogue_kernel() {
    extern __shared__ float sU[];            // [2][32][128] = 32KB
    const int n = 127 + blockIdx.x;
    const int q0 = blockIdx.y * 128;
    const int tid = threadIdx.x;
    for (int idx = tid; idx < 2 * VOCAB * 128; idx += 256) {
        int s = idx >> 12, rem = idx & 4095, t = rem >> 7, j = rem & 127;
        sU[idx] = g_gout[((size_t)s * ROWCAP + t) * GG + q0 + j];
    }
    __syncthreads();

    const int hl = tid & 31;                 // 32 h per 128-q tile
    const int bq = tid >> 5;                 // 8 b-groups
    const int h = (q0 >> 2) + hl;
    const int q = q0 + 4 * hl;
#pragma unroll 1
    for (int bi = 0; bi < 8; bi++) {
        const int b = bq * 8 + bi;
        const int ni = n * BATCH + b;
        const int li = (2 * n + 1) * BATCH + b;
        const int t_node = g_tnode[ni];
        const float dd = g_dnode[ni];
        const int tl = g_tnode[li];
        const float ddl = g_dnode[li];
        const int tr = g_tnode[li + BATCH];
        const int sl = g_slot[(n - 127) * 64 + b];
        const int sr = g_slot[8192 + (n - 127) * 64 + b];
        float4 gL = *(const float4*)&sU[tl * 128 + 4 * hl];
        float4 gR = *(const float4*)&sU[4096 + tr * 128 + 4 * hl];
        float4 g = make_float4(gL.x + gR.x, gL.y + gR.y, gL.z + gR.z, gL.w + gR.w);
        if (sl) {
            float4 cr = *(const float4*)&g_gout[((size_t)0 * ROWCAP + 32 + sl - 1) * GG + q];
            g.x += cr.x; g.y += cr.y; g.z += cr.z; g.w += cr.w;
        }
        if (sr) {
            float4 cr = *(const float4*)&g_gout[((size_t)1 * ROWCAP + 32 + sr - 1) * GG + q];
            g.x += cr.x; g.y += cr.y; g.z += cr.z; g.w += cr.w;
        }
        float c0 = leaf_c(tl, ddl, h);   // left child is a d=8 leaf: closed form
        float hn, cn;
        lstm_cell(g, t_node, dd, q, c0, hn, cn);
        size_t o = (size_t)ni * HH + h;
        g_hhi[o] = __float2bfloat16(hn);
        g_c[o] = cn;
    }
}

// ---------------- level GEMM (d<=6): proven kernel ----------------
__global__ void __launch_bounds__(256, 2) level_mma_kernel(int first, int count, int ksplit) {
    extern __shared__ char smem[];
    uint32_t sb = smem_u32(smem);

    const int tid = threadIdx.x;
    const int lane = tid & 31;
    const int wid = tid >> 5;
    const int warp_m = wid & 3;
    const int warp_n = wid >> 2;

    const int p = blockIdx.x;
    const int n0 = first + 2 * p;
    const int n1 = (n0 + 1 <= first + count - 1) ? n0 + 1 : n0;
    const int q0 = blockIdx.y * BN;
    const int ks = blockIdx.z;
    const int chunks = 16 / ksplit;
    const int kc0 = ks * chunks;
    const int kcE = kc0 + chunks;

    float acc[2][8][4];
#pragma unroll
    for (int mt = 0; mt < 2; mt++)
#pragma unroll
        for (int nt = 0; nt < 8; nt++)
#pragma unroll
            for (int i = 0; i < 4; i++) acc[mt][nt][i] = 0.f;

    auto issue = [&](int kc) {
        const int stage = (kc - kc0) % NSTAGE;
        const int k0 = kc * BK;
        const int cbase = (k0 < 512) ? 1 : 2;
        const int kk = k0 & 511;
        const uint32_t base = sb + stage * ST_SZ;
#pragma unroll
        for (int it = 0; it < 8; it++) {
            int i = tid + it * 256;
            int r = i >> 3, cg = i & 7;
            const void* src;
            if (r < 128) {
                int node = (r < 64) ? n0 : n1;
                src = g_hhi + ((size_t)(2 * node + cbase) * BATCH + (r & 63)) * HH + kk + cg * 8;
            } else {
                src = g_Whi + (size_t)(q0 + r - 128) * 1024 + k0 + cg * 8;
            }
            cp16(base + (uint32_t)(r * TSTRIDE + cg * 16), src);
        }
    };

    issue(kc0);     CP_COMMIT();
    issue(kc0 + 1); CP_COMMIT();

    const uint32_t a_base = (uint32_t)((warp_m * 32 + (lane & 15)) * TSTRIDE + (lane >> 4) * 16);
    const uint32_t b_base = (uint32_t)(128 * TSTRIDE
                             + (warp_n * 64 + ((lane >> 4) << 3) + (lane & 7)) * TSTRIDE
                             + (((lane >> 3) & 1) << 4));

    for (int kc = kc0; kc < kcE; kc++) {
        if (kc < kcE - 1) cp_wait<1>(); else cp_wait<0>();
        __syncthreads();
        if (kc + 2 < kcE) { issue(kc + 2); CP_COMMIT(); }
        const uint32_t base = sb + (uint32_t)(((kc - kc0) % NSTAGE) * ST_SZ);
#pragma unroll
        for (int kt = 0; kt < 4; kt++) {
            uint32_t a[2][4];
            ldm_x4(a[0], base + a_base + kt * 32);
            ldm_x4(a[1], base + a_base + 16 * TSTRIDE + kt * 32);
#pragma unroll
            for (int ng = 0; ng < 4; ng++) {
                uint32_t bh[4];
                ldm_x4(bh, base + b_base + ng * 16 * TSTRIDE + kt * 32);
#pragma unroll
                for (int half = 0; half < 2; half++)
#pragma unroll
                    for (int mt = 0; mt < 2; mt++)
                        mma_bf16(acc[mt][ng * 2 + half], a[mt], bh + 2 * half);
            }
        }
    }

    const int lr = (lane >> 2) + (lane & 1) * 8;
    const int hq = (q0 >> 2) + warp_n * 16 + ((lane & 3) >> 1);

#pragma unroll
    for (int mt = 0; mt < 2; mt++) {
        const int r = warp_m * 32 + mt * 16 + lr;
        const int node = (r < 64) ? n0 : n1;
        const bool skip = (r >= 64) && (n1 == n0);
        const int b = r & 63;
        const int ni = node * BATCH + b;
        const int t = g_tnode[ni];
        const float dd = g_dnode[ni];
        const int left = 2 * node + 1;
#pragma unroll
        for (int nt = 0; nt < 8; nt++) {
            float x0 = __shfl_xor_sync(0xffffffffu, acc[mt][nt][0], 1);
            float x1 = __shfl_xor_sync(0xffffffffu, acc[mt][nt][1], 1);
            float x2 = __shfl_xor_sync(0xffffffffu, acc[mt][nt][2], 1);
            float x3 = __shfl_xor_sync(0xffffffffu, acc[mt][nt][3], 1);
            float4 g;
            if (lane & 1) g = make_float4(x2, x3, acc[mt][nt][2], acc[mt][nt][3]);
            else          g = make_float4(acc[mt][nt][0], acc[mt][nt][1], x0, x1);
            if (skip) continue;
            const int h = hq + nt * 2;
            const int q = 4 * h;
            if (ksplit == 1) {
                float c0 = g_c[((size_t)left * BATCH + b) * HH + h];
                float hn, cn;
                lstm_cell(g, t, dd, q, c0, hn, cn);
                size_t o = ((size_t)node * BATCH + b) * HH + h;
                g_hhi[o] = __float2bfloat16(hn);
                g_c[o] = cn;
                if (node == 0) g_hroot[b * HH + h] = hn;
            } else {
                int nl = node - first;
                size_t dst = (((size_t)(ks * count + nl) * BATCH + b) * (size_t)GG) + q;
                *(float4*)&g_part[dst] = g;
            }
        }
    }
}

// ---------------- split-K reduction + LSTM ----------------
__global__ void level_reduce_kernel(int first, int count, int ksplit) {
    int nl = blockIdx.x;
    int node = first + nl;
    int q0 = blockIdx.y * BN;
    int tid = threadIdx.x;
    for (int idx = tid; idx < 64 * 32; idx += 256) {
        int b = idx >> 5, hg = idx & 31;
        int q = q0 + hg * 4;
        int hidx = (q0 >> 2) + hg;
        float4 s = make_float4(0.f, 0.f, 0.f, 0.f);
        for (int ks = 0; ks < ksplit; ks++) {
            const float4 v = *(const float4*)&g_part[(((size_t)(ks * count + nl) * BATCH + b) * (size_t)GG) + q];
            s.x += v.x; s.y += v.y; s.z += v.z; s.w += v.w;
        }
        int ni = node * BATCH + b;
        int t = g_tnode[ni];
        float dd = g_dnode[ni];
        float c0 = g_c[((size_t)(2 * node + 1) * BATCH + b) * HH + hidx];
        float hn, cn;
        lstm_cell(s, t, dd, q, c0, hn, cn);
        size_t o = ((size_t)node * BATCH + b) * HH + hidx;
        g_hhi[o] = __float2bfloat16(hn);
        g_c[o] = cn;
        if (node == 0) g_hroot[b * HH + hidx] = hn;
    }
}

// ---------------- output head (exact math kept) ----------------
__global__ void head_kernel(const float* __restrict__ W1, const float* __restrict__ b1,
                            const float* __restrict__ W2, const float* __restrict__ b2,
                            const float* __restrict__ validity, float* __restrict__ out) {
    int b = blockIdx.x;
    __shared__ float sh[HH];
    __shared__ float sx[HH];
    __shared__ float slog[OPS];
    const float* rh = g_hroot + (size_t)b * HH;
    for (int i = threadIdx.x; i < HH; i += blockDim.x) sh[i] = rh[i];
    __syncthreads();
    for (int j = threadIdx.x; j < HH; j += blockDim.x) {
        float acc = b1[j];
        const float4* w = (const float4*)(W1 + (size_t)j * HH);
        const float4* s4 = (const float4*)sh;
#pragma unroll 8
        for (int e = 0; e < HH / 4; e++) {
            float4 a = s4[e], ww = w[e];
            acc += a.x * ww.x + a.y * ww.y + a.z * ww.z + a.w * ww.w;
        }
        sx[j] = fmaxf(acc, 0.f);
    }
    __syncthreads();
    int warp = threadIdx.x >> 5, lane = threadIdx.x & 31;
    for (int o = warp; o < OPS; o += 8) {
        float acc = 0.f;
        const float* w = W2 + (size_t)o * HH;
        for (int e = lane; e < HH; e += 32) acc += sx[e] * w[e];
#pragma unroll
        for (int off = 16; off; off >>= 1) acc += __shfl_xor_sync(0xffffffff, acc, off);
        if (lane == 0) slog[o] = acc + b2[o] + logf(validity[b * OPS + o]);
    }
    __syncthreads();
    if (threadIdx.x == 0) {
        float mx = -1e30f;
        float v[OPS];
        for (int o = 0; o < OPS; o++) { v[o] = slog[o] / 3.0f; if (v[o] > mx) mx = v[o]; }
        float s = 0.f;
        for (int o = 0; o < OPS; o++) { v[o] = expf(v[o] - mx); s += v[o]; }
        float inv = 1.0f / s;
        for (int o = 0; o < OPS; o++) out[b * OPS + o] = v[o] * inv;
    }
}

// ---------------- launch ----------------
extern "C" void kernel_launch(void* const* d_in, const int* in_sizes, int n_in,
                              void* d_out, int out_size) {
    const int*   node_types = (const int*)d_in[0];
    const float* node_args  = (const float*)d_in[1];
    const float* validity   = (const float*)d_in[2];
    const float* emb_table  = (const float*)d_in[3];
    const float* W_ih       = (const float*)d_in[4];
    const float* W_hh       = (const float*)d_in[5];
    const float* b_ih       = (const float*)d_in[6];
    const float* b_hh       = (const float*)d_in[7];
    const float* W1         = (const float*)d_in[8];
    const float* b1         = (const float*)d_in[9];
    const float* W2         = (const float*)d_in[10];
    const float* b2         = (const float*)d_in[11];
    float* out = (float*)d_out;

    static bool attr_set = false;
    if (!attr_set) {
        cudaFuncSetAttribute(level_mma_kernel,
                             cudaFuncAttributeMaxDynamicSharedMemorySize, SMEM_BYTES);
        cudaFuncSetAttribute(corrmma_kernel,
                             cudaFuncAttributeMaxDynamicSharedMemorySize, SMEM_BYTES);
        cudaFuncSetAttribute(d7_epilogue_kernel,
                             cudaFuncAttributeMaxDynamicSharedMemorySize, 32768);
        attr_set = true;
    }

    prep_small_kernel<<<(GG + 255) / 256, 256>>>(W_ih, b_ih, b_hh);
    conv_whh_kernel<<<GG, 256>>>(W_hh);
    compP_kernel<<<dim3(VOCAB, GG / 256), 256>>>(emb_table, W_ih);
    node_meta_kernel<<<(PROC * BATCH + 255) / 256, 256>>>(node_types, node_args, emb_table);

    // d=8 + d=7 via dedup path
    compV_kernel<<<VOCAB, 128>>>();
    gather_kernel<<<256, 256>>>();
    corrmma_kernel<<<dim3(ROWCAP / 128 + 1, NTILES, 2), 256, SMEM_BYTES>>>();
    d7_epilogue_kernel<<<dim3(128, 16), 256, 32768>>>();

    // levels d=6..0
    for (int d = 6; d >= 0; --d) {
        int first = (1 << d) - 1;
        int count = 1 << d;
        int sk = (d >= 5) ? 1 : (d == 4 ? 2 : (d == 3 ? 4 : 8));
        dim3 grid((count + 1) / 2, NTILES, sk);
        level_mma_kernel<<<grid, 256, SMEM_BYTES>>>(first, count, sk);
        if (sk > 1)
            level_reduce_kernel<<<dim3(count, NTILES), 256>>>(first, count, sk);
    }

    head_kernel<<<BATCH, 256>>>(W1, b1, W2, b2, validity, out);
}